// round 13
// baseline (speedup 1.0000x reference)
#include <cuda_runtime.h>
#include <math.h>

// Problem constants: N=4, R=16384, K=96
#define KS   96
#define KM   95                 // K-1 midpoint samples
#define RAYS (4 * 16384)        // 65536 rays
#define RPB  8                  // rays per block (1 per warp)

#define FULL  0xffffffffu
#define LOG2E 1.4426950408889634f

__device__ __forceinline__ float ex2f(float x) {
    float r;
    asm("ex2.approx.ftz.f32 %0, %1;" : "=f"(r) : "f"(x));
    return r;
}
__device__ __forceinline__ float lg2f(float x) {
    float r;
    asm("lg2.approx.ftz.f32 %0, %1;" : "=f"(r) : "f"(x));
    return r;
}

// One warp per ray (R8 structure). Changes vs R8:
//  - depth accumulator uses ad = sum_i w_i*(d_i + d_{i+1}) with d1 already in
//    registers from the alpha phase (identity: sum_j d_j*(w_j+w_{j-1}) =
//    sum_i w_i*(d_i+d_{i+1})), so no w_{j-1} shuffles are needed for depth.
//  - smem holds RAW w (zero-padded at index 0: sw[j+1] = w_j); the rgb loop
//    forms ww[i0] = sw[i0]+sw[i0+1] locally. This deletes the entire
//    post-scan shuffle block (wp0..2, b0, b1 + lane-0 selects).
// Everything else identical to the confirmed-best R8 kernel.
__global__ void __launch_bounds__(256) render_kernel(
    const float* __restrict__ rgbs,     // [RAYS, K, 3]
    const float* __restrict__ sigmas,   // [RAYS, K]
    const float* __restrict__ depths,   // [RAYS, K]
    float* __restrict__ out_rgb,        // [RAYS, 3]
    float* __restrict__ out_depth,      // [RAYS]
    float* __restrict__ out_w)          // [RAYS, KM]
{
    __shared__ float sw[RPB][KS + 2];   // sw[0]=0, sw[1+j]=w_j (j=0..95)

    const int t    = threadIdx.x;
    const int warp = t >> 5;
    const int lane = t & 31;
    const int ray  = blockIdx.x * RPB + warp;

    const float*  d   = depths + (size_t)ray * KS;
    const float*  s   = sigmas + (size_t)ray * KS;
    const float4* rg4 = (const float4*)(rgbs + (size_t)ray * KS * 3);
    float* wout       = out_w + (size_t)ray * KM;

    // ---- Front-batched loads: 6 scalar + 2.25 vector LDGs per lane ----
    float dv[3], sv[3];
    #pragma unroll
    for (int c = 0; c < 3; ++c) {
        dv[c] = d[c * 32 + lane];
        sv[c] = s[c * 32 + lane];
    }
    float4 f0 = rg4[lane];
    float4 f1 = rg4[lane + 32];
    float4 f2 = make_float4(0.f, 0.f, 0.f, 0.f);
    if (lane < 8) f2 = rg4[lane + 64];        // 72 float4 = exactly one ray

    // ---- Neighbors via shuffle; keep d1 for the depth identity ----
    float alpha[3], p[3], d1v[3];
    #pragma unroll
    for (int c = 0; c < 3; ++c) {
        bool valid = (c < 2) | (lane < 31);   // only i==95 invalid
        int  cn = (c + 1 < 3) ? c + 1 : 0;    // masked garbage for c==2
        float d1 = __shfl_down_sync(FULL, dv[c], 1);
        float s1 = __shfl_down_sync(FULL, sv[c], 1);
        float dB = __shfl_sync(FULL, dv[cn], 0);
        float sB = __shfl_sync(FULL, sv[cn], 0);
        if (lane == 31) { d1 = dB; s1 = sB; }
        d1v[c] = d1;

        float delta = d1 - dv[c];
        float sm    = 0.5f * (sv[c] + s1) - 1.0f;
        float em    = ex2f(-fabsf(sm) * LOG2E);   // softplus via MUFU ex2/lg2
        float L     = fmaxf(sm, 0.0f) * LOG2E + lg2f(1.0f + em);
        alpha[c]    = 1.0f - ex2f(-delta * L);
        p[c]        = valid ? (1.0f - alpha[c] + 1e-10f) : 1.0f;
    }

    // ---- Three independent inclusive multiplicative scans (ILP=3) ----
    #pragma unroll
    for (int off = 1; off < 32; off <<= 1) {
        float v0 = __shfl_up_sync(FULL, p[0], off);
        float v1 = __shfl_up_sync(FULL, p[1], off);
        float v2 = __shfl_up_sync(FULL, p[2], off);
        if (lane >= off) { p[0] *= v0; p[1] *= v1; p[2] *= v2; }
    }

    float e0 = __shfl_up_sync(FULL, p[0], 1);
    float e1 = __shfl_up_sync(FULL, p[1], 1);
    float e2 = __shfl_up_sync(FULL, p[2], 1);
    if (lane == 0) { e0 = 1.0f; e1 = 1.0f; e2 = 1.0f; }
    float T0 = __shfl_sync(FULL, p[0], 31);
    float T1 = __shfl_sync(FULL, p[1], 31);

    float w0 = alpha[0] * e0;
    float w1 = alpha[1] * (T0 * e1);
    float w2 = alpha[2] * (T0 * T1 * e2);
    if (lane == 31) w2 = 0.0f;                    // w_95 = 0

    wout[lane]      = w0;
    wout[32 + lane] = w1;
    if (lane < 31) wout[64 + lane] = w2;

    // Publish RAW w, zero-padded at index 0 (sw[1+j] = w_j).
    if (lane == 0) sw[warp][0] = 0.0f;
    sw[warp][1 + lane]      = w0;
    sw[warp][33 + lane]     = w1;
    sw[warp][65 + lane]     = w2;                 // lane31 writes sw[96]=0
    __syncwarp();

    // depth / wsum in sample layout: ad = sum w_i*(d_i + d_{i+1})
    float wsum = w0 + w1 + w2;
    float ad = w0 * (dv[0] + d1v[0]);
    ad = fmaf(w1, dv[1] + d1v[1], ad);
    ad = fmaf(w2, dv[2] + d1v[2], ad);

    // ---- rgb accumulation from packed float4s ----
    float accR = 0.f, accG = 0.f, accB = 0.f;
    const float* swp = sw[warp];
    #pragma unroll
    for (int rnd = 0; rnd < 3; ++rnd) {
        if (rnd == 2 && lane >= 8) break;
        float4 f = (rnd == 0) ? f0 : (rnd == 1) ? f1 : f2;
        int m  = lane + rnd * 32;      // float4 index within ray (0..71)
        int eb = 4 * m;                // first element index
        int i0 = eb / 3;               // first sample index
        int ph = eb - 3 * i0;          // channel phase = eb % 3
        float u0 = swp[i0];            // w_{i0-1}
        float u1 = swp[i0 + 1];        // w_{i0}
        float u2 = swp[i0 + 2];        // w_{i0+1}
        float a = u0 + u1;             // ww[i0]
        float b = u1 + u2;             // ww[i0+1]
        // elements eb..eb+3 -> channels (ph, ph+1, ph+2, ph), samples i0/i0+1
        float u  = fmaf(b, f.w, a * f.x);          // sum for channel ph
        float m1 = ((ph == 2) ? b : a) * f.y;      // channel (ph+1)%3
        float m2 = ((ph == 0) ? a : b) * f.z;      // channel (ph+2)%3
        accR += (ph == 0) ? u  : (ph == 1) ? m2 : m1;
        accG += (ph == 0) ? m1 : (ph == 1) ? u  : m2;
        accB += (ph == 0) ? m2 : (ph == 1) ? m1 : u;
    }

    // ---- Warp reduction of the 5 accumulators (R8 tree) ----
    #pragma unroll
    for (int off = 16; off; off >>= 1) {
        wsum += __shfl_down_sync(FULL, wsum, off);
        accR += __shfl_down_sync(FULL, accR, off);
        accG += __shfl_down_sync(FULL, accG, off);
        accB += __shfl_down_sync(FULL, accB, off);
        ad   += __shfl_down_sync(FULL, ad,   off);
    }

    if (lane == 0) {
        out_rgb[ray * 3 + 0] = accR - 1.0f;      // (0.5*S)*2 - 1
        out_rgb[ray * 3 + 1] = accG - 1.0f;
        out_rgb[ray * 3 + 2] = accB - 1.0f;
        out_depth[ray] = (0.5f * ad) / wsum;     // clip/NaN path: no-op
    }
}

extern "C" void kernel_launch(void* const* d_in, const int* in_sizes, int n_in,
                              void* d_out, int out_size) {
    const float* rgbs   = (const float*)d_in[0];
    const float* sigmas = (const float*)d_in[1];
    const float* depths = (const float*)d_in[2];

    float* out = (float*)d_out;
    float* out_rgb   = out;                       // 65536*3
    float* out_depth = out + (size_t)RAYS * 3;    // 65536
    float* out_w     = out + (size_t)RAYS * 4;    // 65536*95

    int blocks = RAYS / RPB;                      // 8192
    render_kernel<<<blocks, 256>>>(rgbs, sigmas, depths, out_rgb, out_depth, out_w);
}

// round 14
// speedup vs baseline: 1.0020x; 1.0020x over previous
#include <cuda_runtime.h>
#include <math.h>

// Problem constants: N=4, R=16384, K=96
#define KS   96
#define KM   95                 // K-1 midpoint samples
#define RAYS (4 * 16384)        // 65536 rays
#define RPB  8                  // rays per block (1 per warp)

#define FULL  0xffffffffu
#define LOG2E 1.4426950408889634f

__device__ __forceinline__ float ex2f(float x) {
    float r;
    asm("ex2.approx.ftz.f32 %0, %1;" : "=f"(r) : "f"(x));
    return r;
}
__device__ __forceinline__ float lg2f(float x) {
    float r;
    asm("lg2.approx.ftz.f32 %0, %1;" : "=f"(r) : "f"(x));
    return r;
}

// Confirmed-best configuration (R8, reproduced at 31.20/31.23 us).
// One warp per ray. d/s: scalar loads + neighbor shuffles. rgb: packed
// LDG.128 (72 float4 per ray = 2.25/lane) -- rgb is only needed for the dot
// products sum_j x_j * ww_j, so instead of redistributing rgb into sample
// layout we redistribute the WEIGHTS: ww_j (j=0..95, with w_95=0) goes to a
// per-warp smem array; each lane then reads the two weights its float4 spans
// and routes the 4 products into R/G/B accumulators by channel phase.
//  - midpoint identity: sum_i w_i*0.5*(x_i+x_{i+1}) = 0.5*sum_j x_j*(w_j+w_{j-1})
//  - final rgb = (0.5*S)*2 - 1 = S - 1
//  - global depth clip + NaN path are provable no-ops (convex combination of
//    the ray's own midpoints; wsum > 0 since softplus > 0, sorted deltas > 0).
__global__ void __launch_bounds__(256) render_kernel(
    const float* __restrict__ rgbs,     // [RAYS, K, 3]
    const float* __restrict__ sigmas,   // [RAYS, K]
    const float* __restrict__ depths,   // [RAYS, K]
    float* __restrict__ out_rgb,        // [RAYS, 3]
    float* __restrict__ out_depth,      // [RAYS]
    float* __restrict__ out_w)          // [RAYS, KM]
{
    __shared__ float sww[RPB][KS];      // 96 weights per warp (3 KB total)

    const int t    = threadIdx.x;
    const int warp = t >> 5;
    const int lane = t & 31;
    const int ray  = blockIdx.x * RPB + warp;

    const float*  d   = depths + (size_t)ray * KS;
    const float*  s   = sigmas + (size_t)ray * KS;
    const float4* rg4 = (const float4*)(rgbs + (size_t)ray * KS * 3);
    float* wout       = out_w + (size_t)ray * KM;

    // ---- Front-batched loads: 6 scalar + 2.25 vector LDGs per lane ----
    float dv[3], sv[3];
    #pragma unroll
    for (int c = 0; c < 3; ++c) {
        dv[c] = d[c * 32 + lane];
        sv[c] = s[c * 32 + lane];
    }
    float4 f0 = rg4[lane];
    float4 f1 = rg4[lane + 32];
    float4 f2 = make_float4(0.f, 0.f, 0.f, 0.f);
    if (lane < 8) f2 = rg4[lane + 64];        // 72 float4 = exactly one ray

    // ---- Neighbors via shuffle (chunk boundary from next chunk's lane 0) ----
    float alpha[3], p[3];
    #pragma unroll
    for (int c = 0; c < 3; ++c) {
        bool valid = (c < 2) | (lane < 31);   // only i==95 invalid
        int  cn = (c + 1 < 3) ? c + 1 : 0;    // masked garbage for c==2
        float d1 = __shfl_down_sync(FULL, dv[c], 1);
        float s1 = __shfl_down_sync(FULL, sv[c], 1);
        float dB = __shfl_sync(FULL, dv[cn], 0);
        float sB = __shfl_sync(FULL, sv[cn], 0);
        if (lane == 31) { d1 = dB; s1 = sB; }

        float delta = d1 - dv[c];
        float sm    = 0.5f * (sv[c] + s1) - 1.0f;
        float em    = ex2f(-fabsf(sm) * LOG2E);   // softplus via MUFU ex2/lg2
        float L     = fmaxf(sm, 0.0f) * LOG2E + lg2f(1.0f + em);
        alpha[c]    = 1.0f - ex2f(-delta * L);
        p[c]        = valid ? (1.0f - alpha[c] + 1e-10f) : 1.0f;
    }

    // ---- Three independent inclusive multiplicative scans (ILP=3) ----
    #pragma unroll
    for (int off = 1; off < 32; off <<= 1) {
        float v0 = __shfl_up_sync(FULL, p[0], off);
        float v1 = __shfl_up_sync(FULL, p[1], off);
        float v2 = __shfl_up_sync(FULL, p[2], off);
        if (lane >= off) { p[0] *= v0; p[1] *= v1; p[2] *= v2; }
    }

    float e0 = __shfl_up_sync(FULL, p[0], 1);
    float e1 = __shfl_up_sync(FULL, p[1], 1);
    float e2 = __shfl_up_sync(FULL, p[2], 1);
    if (lane == 0) { e0 = 1.0f; e1 = 1.0f; e2 = 1.0f; }
    float T0 = __shfl_sync(FULL, p[0], 31);
    float T1 = __shfl_sync(FULL, p[1], 31);

    float w0 = alpha[0] * e0;
    float w1 = alpha[1] * (T0 * e1);
    float w2 = alpha[2] * (T0 * T1 * e2);
    if (lane == 31) w2 = 0.0f;                    // w_95 = 0

    wout[lane]      = w0;
    wout[32 + lane] = w1;
    if (lane < 31) wout[64 + lane] = w2;

    // ww_j = w_j + w_{j-1}  (j = 0..95)
    float wp0 = __shfl_up_sync(FULL, w0, 1);
    float wp1 = __shfl_up_sync(FULL, w1, 1);
    float wp2 = __shfl_up_sync(FULL, w2, 1);
    float b0  = __shfl_sync(FULL, w0, 31);
    float b1  = __shfl_sync(FULL, w1, 31);
    if (lane == 0) { wp0 = 0.0f; wp1 = b0; wp2 = b1; }
    float ww0 = w0 + wp0, ww1 = w1 + wp1, ww2 = w2 + wp2;

    // Publish weights for the float4-layout rgb accumulation.
    sww[warp][lane]      = ww0;
    sww[warp][32 + lane] = ww1;
    sww[warp][64 + lane] = ww2;
    __syncwarp();

    // depth / wsum from sample layout
    float wsum = w0 + w1 + w2;
    float ad = ww0 * dv[0];
    ad = fmaf(ww1, dv[1], ad);
    ad = fmaf(ww2, dv[2], ad);

    // ---- rgb accumulation from packed float4s ----
    float accR = 0.f, accG = 0.f, accB = 0.f;
    const float* wwp = sww[warp];
    #pragma unroll
    for (int rnd = 0; rnd < 3; ++rnd) {
        if (rnd == 2 && lane >= 8) break;
        float4 f = (rnd == 0) ? f0 : (rnd == 1) ? f1 : f2;
        int m  = lane + rnd * 32;      // float4 index within ray (0..71)
        int eb = 4 * m;                // first element index
        int i0 = eb / 3;               // first sample index
        int ph = eb - 3 * i0;          // channel phase = eb % 3
        float a = wwp[i0];
        float b = wwp[i0 + 1];
        // elements eb..eb+3 -> channels (ph, ph+1, ph+2, ph), samples i0/i0+1
        float u  = fmaf(b, f.w, a * f.x);          // sum for channel ph
        float m1 = ((ph == 2) ? b : a) * f.y;      // channel (ph+1)%3
        float m2 = ((ph == 0) ? a : b) * f.z;      // channel (ph+2)%3
        accR += (ph == 0) ? u  : (ph == 1) ? m2 : m1;
        accG += (ph == 0) ? m1 : (ph == 1) ? u  : m2;
        accB += (ph == 0) ? m2 : (ph == 1) ? m1 : u;
    }

    // ---- Warp reduction of the 5 accumulators ----
    #pragma unroll
    for (int off = 16; off; off >>= 1) {
        wsum += __shfl_down_sync(FULL, wsum, off);
        accR += __shfl_down_sync(FULL, accR, off);
        accG += __shfl_down_sync(FULL, accG, off);
        accB += __shfl_down_sync(FULL, accB, off);
        ad   += __shfl_down_sync(FULL, ad,   off);
    }

    if (lane == 0) {
        out_rgb[ray * 3 + 0] = accR - 1.0f;      // (0.5*S)*2 - 1
        out_rgb[ray * 3 + 1] = accG - 1.0f;
        out_rgb[ray * 3 + 2] = accB - 1.0f;
        out_depth[ray] = (0.5f * ad) / wsum;     // clip/NaN path: no-op
    }
}

extern "C" void kernel_launch(void* const* d_in, const int* in_sizes, int n_in,
                              void* d_out, int out_size) {
    const float* rgbs   = (const float*)d_in[0];
    const float* sigmas = (const float*)d_in[1];
    const float* depths = (const float*)d_in[2];

    float* out = (float*)d_out;
    float* out_rgb   = out;                       // 65536*3
    float* out_depth = out + (size_t)RAYS * 3;    // 65536
    float* out_w     = out + (size_t)RAYS * 4;    // 65536*95

    int blocks = RAYS / RPB;                      // 8192
    render_kernel<<<blocks, 256>>>(rgbs, sigmas, depths, out_rgb, out_depth, out_w);
}

// round 15
// speedup vs baseline: 1.0533x; 1.0513x over previous
#include <cuda_runtime.h>
#include <math.h>

// Problem constants: N=4, R=16384, K=96
#define KS   96
#define KM   95                 // K-1 midpoint samples
#define RAYS (4 * 16384)        // 65536 rays
#define RPB  8                  // rays per block (1 per warp)

#define FULL  0xffffffffu
#define LOG2E 1.4426950408889634f

__device__ __forceinline__ float ex2f(float x) {
    float r;
    asm("ex2.approx.ftz.f32 %0, %1;" : "=f"(r) : "f"(x));
    return r;
}
__device__ __forceinline__ float lg2f(float x) {
    float r;
    asm("lg2.approx.ftz.f32 %0, %1;" : "=f"(r) : "f"(x));
    return r;
}

// FINAL kernel — confirmed-best configuration (measured 31.20/31.23/32.80 us
// across three runs; bench noise ~±0.8 us).
//
// One warp per ray. d/s: scalar coalesced loads + neighbor shuffles.
// rgb: packed LDG.128 (72 float4 per ray = 2.25/lane) — rgb is only needed
// for the dot products sum_j x_j * ww_j, so instead of redistributing rgb
// into sample layout we redistribute the WEIGHTS: ww_j (j=0..95, w_95=0)
// goes to a per-warp smem array; each lane reads the two weights its float4
// spans and routes the 4 products into R/G/B accumulators by channel phase.
//
// Math notes:
//  - transmittance: 3 interleaved Hillis-Steele multiplicative warp scans
//    (ILP=3), cross-chunk coupling via chunk-total products.
//  - midpoint identity: sum_i w_i*0.5*(x_i+x_{i+1}) = 0.5*sum_j x_j*(w_j+w_{j-1})
//  - final rgb = (0.5*S)*2 - 1 = S - 1
//  - softplus via MUFU ex2/lg2 (stable form), alpha = 1 - ex2(-delta*L)
//  - global depth clip + NaN path are provable no-ops (composite depth is a
//    convex combination of the ray's own midpoints; wsum > 0 since
//    softplus > 0 and sorted deltas > 0).
__global__ void __launch_bounds__(256) render_kernel(
    const float* __restrict__ rgbs,     // [RAYS, K, 3]
    const float* __restrict__ sigmas,   // [RAYS, K]
    const float* __restrict__ depths,   // [RAYS, K]
    float* __restrict__ out_rgb,        // [RAYS, 3]
    float* __restrict__ out_depth,      // [RAYS]
    float* __restrict__ out_w)          // [RAYS, KM]
{
    __shared__ float sww[RPB][KS];      // 96 weights per warp (3 KB total)

    const int t    = threadIdx.x;
    const int warp = t >> 5;
    const int lane = t & 31;
    const int ray  = blockIdx.x * RPB + warp;

    const float*  d   = depths + (size_t)ray * KS;
    const float*  s   = sigmas + (size_t)ray * KS;
    const float4* rg4 = (const float4*)(rgbs + (size_t)ray * KS * 3);
    float* wout       = out_w + (size_t)ray * KM;

    // ---- Front-batched loads: 6 scalar + 2.25 vector LDGs per lane ----
    float dv[3], sv[3];
    #pragma unroll
    for (int c = 0; c < 3; ++c) {
        dv[c] = d[c * 32 + lane];
        sv[c] = s[c * 32 + lane];
    }
    float4 f0 = rg4[lane];
    float4 f1 = rg4[lane + 32];
    float4 f2 = make_float4(0.f, 0.f, 0.f, 0.f);
    if (lane < 8) f2 = rg4[lane + 64];        // 72 float4 = exactly one ray

    // ---- Neighbors via shuffle (chunk boundary from next chunk's lane 0) ----
    float alpha[3], p[3];
    #pragma unroll
    for (int c = 0; c < 3; ++c) {
        bool valid = (c < 2) | (lane < 31);   // only i==95 invalid
        int  cn = (c + 1 < 3) ? c + 1 : 0;    // masked garbage for c==2
        float d1 = __shfl_down_sync(FULL, dv[c], 1);
        float s1 = __shfl_down_sync(FULL, sv[c], 1);
        float dB = __shfl_sync(FULL, dv[cn], 0);
        float sB = __shfl_sync(FULL, sv[cn], 0);
        if (lane == 31) { d1 = dB; s1 = sB; }

        float delta = d1 - dv[c];
        float sm    = 0.5f * (sv[c] + s1) - 1.0f;
        float em    = ex2f(-fabsf(sm) * LOG2E);   // softplus via MUFU ex2/lg2
        float L     = fmaxf(sm, 0.0f) * LOG2E + lg2f(1.0f + em);
        alpha[c]    = 1.0f - ex2f(-delta * L);
        p[c]        = valid ? (1.0f - alpha[c] + 1e-10f) : 1.0f;
    }

    // ---- Three independent inclusive multiplicative scans (ILP=3) ----
    #pragma unroll
    for (int off = 1; off < 32; off <<= 1) {
        float v0 = __shfl_up_sync(FULL, p[0], off);
        float v1 = __shfl_up_sync(FULL, p[1], off);
        float v2 = __shfl_up_sync(FULL, p[2], off);
        if (lane >= off) { p[0] *= v0; p[1] *= v1; p[2] *= v2; }
    }

    float e0 = __shfl_up_sync(FULL, p[0], 1);
    float e1 = __shfl_up_sync(FULL, p[1], 1);
    float e2 = __shfl_up_sync(FULL, p[2], 1);
    if (lane == 0) { e0 = 1.0f; e1 = 1.0f; e2 = 1.0f; }
    float T0 = __shfl_sync(FULL, p[0], 31);
    float T1 = __shfl_sync(FULL, p[1], 31);

    float w0 = alpha[0] * e0;
    float w1 = alpha[1] * (T0 * e1);
    float w2 = alpha[2] * (T0 * T1 * e2);
    if (lane == 31) w2 = 0.0f;                    // w_95 = 0

    wout[lane]      = w0;
    wout[32 + lane] = w1;
    if (lane < 31) wout[64 + lane] = w2;

    // ww_j = w_j + w_{j-1}  (j = 0..95)
    float wp0 = __shfl_up_sync(FULL, w0, 1);
    float wp1 = __shfl_up_sync(FULL, w1, 1);
    float wp2 = __shfl_up_sync(FULL, w2, 1);
    float b0  = __shfl_sync(FULL, w0, 31);
    float b1  = __shfl_sync(FULL, w1, 31);
    if (lane == 0) { wp0 = 0.0f; wp1 = b0; wp2 = b1; }
    float ww0 = w0 + wp0, ww1 = w1 + wp1, ww2 = w2 + wp2;

    // Publish weights for the float4-layout rgb accumulation.
    sww[warp][lane]      = ww0;
    sww[warp][32 + lane] = ww1;
    sww[warp][64 + lane] = ww2;
    __syncwarp();

    // depth / wsum from sample layout
    float wsum = w0 + w1 + w2;
    float ad = ww0 * dv[0];
    ad = fmaf(ww1, dv[1], ad);
    ad = fmaf(ww2, dv[2], ad);

    // ---- rgb accumulation from packed float4s ----
    float accR = 0.f, accG = 0.f, accB = 0.f;
    const float* wwp = sww[warp];
    #pragma unroll
    for (int rnd = 0; rnd < 3; ++rnd) {
        if (rnd == 2 && lane >= 8) break;
        float4 f = (rnd == 0) ? f0 : (rnd == 1) ? f1 : f2;
        int m  = lane + rnd * 32;      // float4 index within ray (0..71)
        int eb = 4 * m;                // first element index
        int i0 = eb / 3;               // first sample index
        int ph = eb - 3 * i0;          // channel phase = eb % 3
        float a = wwp[i0];
        float b = wwp[i0 + 1];
        // elements eb..eb+3 -> channels (ph, ph+1, ph+2, ph), samples i0/i0+1
        float u  = fmaf(b, f.w, a * f.x);          // sum for channel ph
        float m1 = ((ph == 2) ? b : a) * f.y;      // channel (ph+1)%3
        float m2 = ((ph == 0) ? a : b) * f.z;      // channel (ph+2)%3
        accR += (ph == 0) ? u  : (ph == 1) ? m2 : m1;
        accG += (ph == 0) ? m1 : (ph == 1) ? u  : m2;
        accB += (ph == 0) ? m2 : (ph == 1) ? m1 : u;
    }

    // ---- Warp reduction of the 5 accumulators ----
    #pragma unroll
    for (int off = 16; off; off >>= 1) {
        wsum += __shfl_down_sync(FULL, wsum, off);
        accR += __shfl_down_sync(FULL, accR, off);
        accG += __shfl_down_sync(FULL, accG, off);
        accB += __shfl_down_sync(FULL, accB, off);
        ad   += __shfl_down_sync(FULL, ad,   off);
    }

    if (lane == 0) {
        out_rgb[ray * 3 + 0] = accR - 1.0f;      // (0.5*S)*2 - 1
        out_rgb[ray * 3 + 1] = accG - 1.0f;
        out_rgb[ray * 3 + 2] = accB - 1.0f;
        out_depth[ray] = (0.5f * ad) / wsum;     // clip/NaN path: no-op
    }
}

extern "C" void kernel_launch(void* const* d_in, const int* in_sizes, int n_in,
                              void* d_out, int out_size) {
    const float* rgbs   = (const float*)d_in[0];
    const float* sigmas = (const float*)d_in[1];
    const float* depths = (const float*)d_in[2];

    float* out = (float*)d_out;
    float* out_rgb   = out;                       // 65536*3
    float* out_depth = out + (size_t)RAYS * 3;    // 65536
    float* out_w     = out + (size_t)RAYS * 4;    // 65536*95

    int blocks = RAYS / RPB;                      // 8192
    render_kernel<<<blocks, 256>>>(rgbs, sigmas, depths, out_rgb, out_depth, out_w);
}